// round 5
// baseline (speedup 1.0000x reference)
#include <cuda_runtime.h>
#include <math.h>

#define N   384
#define C   128
#define H   4
#define DH  32
#define NN  (N*N)
#define KS  36          // Ksh row stride (floats, mult of 4 -> 16B-aligned rows)
#define VS2 33          // Vsh2 row stride in float2 units

typedef unsigned long long ull;

// Scratch (allocation-free rule: __device__ globals)
__device__ float g_x[NN*C];
__device__ float g_q[NN*C];
__device__ float g_k[NN*C];
__device__ float g_v[NN*C];
__device__ float g_g[NN*C];
__device__ float g_o[NN*C];
__device__ float g_bias[H*NN];

// --------------------------- f32x2 helpers ---------------------------------
__device__ __forceinline__ void ffma2(ull& d, ull a, ull b, ull c) {
    asm("fma.rn.f32x2 %0, %1, %2, %3;" : "=l"(d) : "l"(a), "l"(b), "l"(c));
}
__device__ __forceinline__ ull pack_dup(float a) {
    ull r; asm("mov.b64 %0, {%1, %1};" : "=l"(r) : "f"(a)); return r;
}
__device__ __forceinline__ float hsum2(ull a) {
    float lo, hi; asm("mov.b64 {%0, %1}, %2;" : "=f"(lo), "=f"(hi) : "l"(a));
    return lo + hi;
}

// ---------------------------------------------------------------------------
// LayerNorm over C + per-head pair bias. One warp per 2 rows, float4 lanes.
// ---------------------------------------------------------------------------
__global__ void ln_bias_kernel(const float* __restrict__ pair,
                               const float* __restrict__ ln_w,
                               const float* __restrict__ ln_b,
                               const float* __restrict__ w_bias) {
    int warp = threadIdx.x >> 5, lane = threadIdx.x & 31;
    int row0 = (blockIdx.x * 8 + warp) * 2;
    float4 lw = ((const float4*)ln_w)[lane];
    float4 lb = ((const float4*)ln_b)[lane];
    float4 wb0 = ((const float4*)w_bias)[lane*4 + 0];
    float4 wb1 = ((const float4*)w_bias)[lane*4 + 1];
    float4 wb2 = ((const float4*)w_bias)[lane*4 + 2];
    float4 wb3 = ((const float4*)w_bias)[lane*4 + 3];

    #pragma unroll
    for (int rr = 0; rr < 2; rr++) {
        int row = row0 + rr;
        float4 x = ((const float4*)(pair + (size_t)row * C))[lane];
        float s = x.x + x.y + x.z + x.w;
        #pragma unroll
        for (int o = 16; o; o >>= 1) s += __shfl_xor_sync(0xffffffffu, s, o);
        float mu = s * (1.0f / C);
        float dx = x.x-mu, dy = x.y-mu, dz = x.z-mu, dw = x.w-mu;
        float s2 = dx*dx + dy*dy + dz*dz + dw*dw;
        #pragma unroll
        for (int o = 16; o; o >>= 1) s2 += __shfl_xor_sync(0xffffffffu, s2, o);
        float rstd = rsqrtf(s2 * (1.0f / C) + 1e-5f);
        float4 y;
        y.x = dx*rstd*lw.x + lb.x;
        y.y = dy*rstd*lw.y + lb.y;
        y.z = dz*rstd*lw.z + lb.z;
        y.w = dw*rstd*lw.w + lb.w;
        ((float4*)(g_x + (size_t)row * C))[lane] = y;

        float4 bs;
        bs.x = y.x*wb0.x + y.y*wb1.x + y.z*wb2.x + y.w*wb3.x;
        bs.y = y.x*wb0.y + y.y*wb1.y + y.z*wb2.y + y.w*wb3.y;
        bs.z = y.x*wb0.z + y.y*wb1.z + y.z*wb2.z + y.w*wb3.z;
        bs.w = y.x*wb0.w + y.y*wb1.w + y.z*wb2.w + y.w*wb3.w;
        #pragma unroll
        for (int o = 16; o; o >>= 1) {
            bs.x += __shfl_xor_sync(0xffffffffu, bs.x, o);
            bs.y += __shfl_xor_sync(0xffffffffu, bs.y, o);
            bs.z += __shfl_xor_sync(0xffffffffu, bs.z, o);
            bs.w += __shfl_xor_sync(0xffffffffu, bs.w, o);
        }
        if (lane == 0) {
            g_bias[0*NN + row] = bs.x;
            g_bias[1*NN + row] = bs.y;
            g_bias[2*NN + row] = bs.z;
            g_bias[3*NN + row] = bs.w;
        }
    }
}

// ---------------------------------------------------------------------------
// Fused multi-weight SGEMM. Block tile 128 rows x 64 cols, 8x4 register tile,
// inner product in packed f32x2 (2 FFMA2 per (r,kk) on adjacent W columns).
// ---------------------------------------------------------------------------
__global__ __launch_bounds__(256) void gemm_fused_kernel(
    const float* __restrict__ A, const float* __restrict__ A2,
    const float* __restrict__ W0, const float* __restrict__ W1,
    const float* __restrict__ W2, const float* __restrict__ W3,
    float* __restrict__ O0, float* __restrict__ O1,
    float* __restrict__ O2, float* __restrict__ O3,
    int nit, int sigmask)
{
    extern __shared__ float sm[];
    float* As = sm;             // [128][128]
    float* Ws = sm + 128*128;   // [128][64]
    const float* Wlist[4] = {W0, W1, W2, W3};
    float*       Olist[4] = {O0, O1, O2, O3};

    int rowBase = blockIdx.x * 128;
    int tid = threadIdx.x;
    const float* Ap = A + (size_t)rowBase * C;
    if (A2) {
        const float* A2p = A2 + (size_t)rowBase * C;
        #pragma unroll
        for (int i = tid*4; i < 128*128; i += 1024) {
            float4 a = *(const float4*)&Ap[i];
            float4 b = *(const float4*)&A2p[i];
            a.x *= b.x; a.y *= b.y; a.z *= b.z; a.w *= b.w;
            *(float4*)&As[i] = a;
        }
    } else {
        #pragma unroll
        for (int i = tid*4; i < 128*128; i += 1024)
            *(float4*)&As[i] = *(const float4*)&Ap[i];
    }

    int tx = tid & 15, ty = tid >> 4;

    for (int it = 0; it < nit; it++) {
        int w = it >> 1;
        int colBase = (it & 1) * 64;
        const float* W = Wlist[w];
        __syncthreads();
        #pragma unroll
        for (int i = tid*4; i < 128*64; i += 1024) {
            int kr = i >> 6, kc = i & 63;
            *(float4*)&Ws[i] = *(const float4*)&W[kr * C + colBase + kc];
        }
        __syncthreads();

        ull acc2[8][2];
        #pragma unroll
        for (int r = 0; r < 8; r++) { acc2[r][0] = 0ull; acc2[r][1] = 0ull; }

        for (int k0 = 0; k0 < 128; k0 += 4) {
            float av[8][4]; ulonglong2 bv[4];
            #pragma unroll
            for (int kk = 0; kk < 4; kk++)
                bv[kk] = *(const ulonglong2*)&Ws[(k0 + kk)*64 + tx*4];
            #pragma unroll
            for (int r = 0; r < 8; r++)
                *(float4*)av[r] = *(const float4*)&As[(ty*8 + r)*128 + k0];
            #pragma unroll
            for (int r = 0; r < 8; r++)
                #pragma unroll
                for (int kk = 0; kk < 4; kk++) {
                    ull a2 = pack_dup(av[r][kk]);
                    ffma2(acc2[r][0], a2, bv[kk].x, acc2[r][0]);
                    ffma2(acc2[r][1], a2, bv[kk].y, acc2[r][1]);
                }
        }

        int sig = (sigmask >> w) & 1;
        float* O = Olist[w];
        #pragma unroll
        for (int r = 0; r < 8; r++) {
            float lo0, hi0, lo1, hi1;
            asm("mov.b64 {%0, %1}, %2;" : "=f"(lo0), "=f"(hi0) : "l"(acc2[r][0]));
            asm("mov.b64 {%0, %1}, %2;" : "=f"(lo1), "=f"(hi1) : "l"(acc2[r][1]));
            float4 v = make_float4(lo0, hi0, lo1, hi1);
            if (sig) {
                v.x = 1.f/(1.f + __expf(-v.x));
                v.y = 1.f/(1.f + __expf(-v.y));
                v.z = 1.f/(1.f + __expf(-v.z));
                v.w = 1.f/(1.f + __expf(-v.w));
            }
            *(float4*)&O[((size_t)rowBase + ty*8 + r)*C + colBase + tx*4] = v;
        }
    }
}

// ---------------------------------------------------------------------------
// Attention: one block (256 thr, 8 warps) per (b,h). 8 q-rows per warp-group
// amortize every K/V smem read. QK: 4 passes x 3 k-columns, d paired via
// f32x2 with LDS.128 K reads. Softmax stores UNNORMALIZED exp; 1/s folded
// into the O store. PV: paired over k with pre-packed V, shared by 8 rows.
// ---------------------------------------------------------------------------
__global__ __launch_bounds__(256) void attn_kernel(const int* __restrict__ mask) {
    extern __shared__ float sm[];
    float* Ksh   = sm;                        // [384][36]
    float* Vsh2f = Ksh + N*KS;                // 192 x [VS2 float2] (packed k-pairs)
    float* Psh   = Vsh2f + 192*VS2*2;         // 8 warps x [8][384]
    float* Qsh   = Psh + 8*8*N;               // 8 warps x [8][32]
    int b = blockIdx.x, h = blockIdx.y;
    int tid = threadIdx.x, warp = tid >> 5, lane = tid & 31;

    const float* Kg = g_k + (size_t)b*N*C + h*DH;
    const float* Vg = g_v + (size_t)b*N*C + h*DH;
    for (int i = tid; i < N*DH; i += 256) {
        int r = i >> 5, d = i & 31;
        Ksh[r*KS + d] = Kg[(size_t)r*C + d];
        // pack V k-pairs: Vsh2[k>>1][d] = {V[k_even][d], V[k_odd][d]}
        Vsh2f[(r >> 1)*(VS2*2) + d*2 + (r & 1)] = Vg[(size_t)r*C + d];
    }
    __syncthreads();

    bool mk[12];
    const int* mrow = mask + b*N;
    #pragma unroll
    for (int i = 0; i < 12; i++) mk[i] = mrow[lane + 32*i] > 0;

    float* Pw = Psh + warp * (8*N);
    float* Qw = Qsh + warp * 256;
    const ull* V2 = (const ull*)Vsh2f;
    const float* biasH = g_bias + (size_t)h*NN;
    const float scale = 0.17677669529663687f;   // 1/sqrt(32)

    for (int grp = warp; grp < 48; grp += 8) {
        int q0 = grp * 8;
        #pragma unroll
        for (int r = 0; r < 8; r++)
            Qw[r*32 + lane] = g_q[((size_t)b*N + q0 + r)*C + h*DH + lane];
        __syncwarp();

        // ---- QK: 4 passes of 3 k-columns; 8 rows share each K read ----
        #pragma unroll
        for (int pass = 0; pass < 4; pass++) {
            ull acc2[8][3];
            #pragma unroll
            for (int r = 0; r < 8; r++)
                #pragma unroll
                for (int ii = 0; ii < 3; ii++) acc2[r][ii] = 0ull;

            #pragma unroll 2
            for (int dp = 0; dp < 8; dp++) {      // 4 d per iter
                ulonglong2 q2[8];
                #pragma unroll
                for (int r = 0; r < 8; r++)
                    q2[r] = *(const ulonglong2*)&Qw[r*32 + 4*dp];
                #pragma unroll
                for (int ii = 0; ii < 3; ii++) {
                    int i = pass*3 + ii;
                    ulonglong2 k2 = *(const ulonglong2*)&Ksh[(lane + 32*i)*KS + 4*dp];
                    #pragma unroll
                    for (int r = 0; r < 8; r++) {
                        ffma2(acc2[r][ii], q2[r].x, k2.x, acc2[r][ii]);
                        ffma2(acc2[r][ii], q2[r].y, k2.y, acc2[r][ii]);
                    }
                }
            }
            #pragma unroll
            for (int r = 0; r < 8; r++)
                #pragma unroll
                for (int ii = 0; ii < 3; ii++)
                    Pw[r*N + lane + 32*(pass*3 + ii)] = hsum2(acc2[r][ii]);
        }

        // ---- softmax: raw logits -> unnormalized exp (1/s kept per row) ----
        float inv8[8];
        #pragma unroll
        for (int r = 0; r < 8; r++) {
            const float* brow = biasH + (size_t)(q0 + r)*N;
            float vals[12];
            float m = -3.0e38f;
            #pragma unroll
            for (int i = 0; i < 12; i++) {
                float v = mk[i] ? (Pw[r*N + lane + 32*i]*scale + brow[lane + 32*i])
                                : -1e9f;
                vals[i] = v;
                m = fmaxf(m, v);
            }
            #pragma unroll
            for (int o = 16; o; o >>= 1) m = fmaxf(m, __shfl_xor_sync(0xffffffffu, m, o));
            float s = 0.f;
            #pragma unroll
            for (int i = 0; i < 12; i++) { float e = __expf(vals[i] - m); vals[i] = e; s += e; }
            #pragma unroll
            for (int o = 16; o; o >>= 1) s += __shfl_xor_sync(0xffffffffu, s, o);
            inv8[r] = 1.f / s;
            #pragma unroll
            for (int i = 0; i < 12; i++) Pw[r*N + lane + 32*i] = vals[i];
        }
        __syncwarp();

        // ---- PV: paired over k; each V pair shared by 8 rows ----
        ull o2[8];
        #pragma unroll
        for (int r = 0; r < 8; r++) o2[r] = 0ull;
        #pragma unroll 2
        for (int k0 = 0; k0 < N; k0 += 4) {
            int k2a = k0 >> 1;
            ull va = V2[(size_t)k2a*VS2 + lane];
            ull vb = V2[(size_t)(k2a+1)*VS2 + lane];
            #pragma unroll
            for (int r = 0; r < 8; r++) {
                ulonglong2 pp = *(const ulonglong2*)&Pw[r*N + k0];
                ffma2(o2[r], pp.x, va, o2[r]);
                ffma2(o2[r], pp.y, vb, o2[r]);
            }
        }
        float* Og = g_o + ((size_t)b*N + q0)*C + h*DH + lane;
        #pragma unroll
        for (int r = 0; r < 8; r++) Og[r*C] = hsum2(o2[r]) * inv8[r];
        __syncwarp();
    }
}

// ---------------------------------------------------------------------------
extern "C" void kernel_launch(void* const* d_in, const int* in_sizes, int n_in,
                              void* d_out, int out_size) {
    const float* pair   = (const float*)d_in[0];
    const int*   mask   = (const int*)  d_in[1];
    const float* ln_w   = (const float*)d_in[2];
    const float* ln_b   = (const float*)d_in[3];
    const float* w_bias = (const float*)d_in[4];
    const float* wq     = (const float*)d_in[5];
    const float* wk     = (const float*)d_in[6];
    const float* wv     = (const float*)d_in[7];
    const float* wg     = (const float*)d_in[8];
    const float* wo     = (const float*)d_in[9];

    float *gx, *gq, *gk, *gv, *gg, *go;
    cudaGetSymbolAddress((void**)&gx, g_x);
    cudaGetSymbolAddress((void**)&gq, g_q);
    cudaGetSymbolAddress((void**)&gk, g_k);
    cudaGetSymbolAddress((void**)&gv, g_v);
    cudaGetSymbolAddress((void**)&gg, g_g);
    cudaGetSymbolAddress((void**)&go, g_o);

    size_t gemm_smem = (size_t)(128*128 + 128*64) * sizeof(float);   // 96 KB
    size_t attn_smem = (size_t)(N*KS + 192*VS2*2 + 8*8*N + 8*256) * sizeof(float); // ~212.5 KB
    cudaFuncSetAttribute(gemm_fused_kernel, cudaFuncAttributeMaxDynamicSharedMemorySize,
                         (int)gemm_smem);
    cudaFuncSetAttribute(attn_kernel, cudaFuncAttributeMaxDynamicSharedMemorySize,
                         (int)attn_smem);

    ln_bias_kernel<<<NN/16, 256>>>(pair, ln_w, ln_b, w_bias);

    // Fused Q/K/V/Gate projections (gate gets sigmoid: w index 3 -> bit 3)
    gemm_fused_kernel<<<NN/128, 256, gemm_smem>>>(
        gx, nullptr, wq, wk, wv, wg, gq, gk, gv, gg, 8, 8);

    attn_kernel<<<dim3(N, H), 256, attn_smem>>>(mask);

    // Output projection: (o * gate) @ wo
    gemm_fused_kernel<<<NN/128, 256, gemm_smem>>>(
        go, gg, wo, nullptr, nullptr, nullptr, (float*)d_out, nullptr, nullptr, nullptr, 2, 0);
}